// round 2
// baseline (speedup 1.0000x reference)
#include <cuda_runtime.h>
#include <math.h>

// Problem constants
#define Bq   16
#define SS   512
#define EE   512
#define HH   8
#define FF   2048
#define LL   6
#define DH   64
#define NTOK (Bq * SS)           // 8192 tokens
#define E3   (3 * EE)            // 1536

// ---------------- scratch (device globals; no runtime allocation) ------------
__device__ float g_x[NTOK * EE];                 // 16 MB  activations
__device__ float g_qkv[NTOK * E3];               // 48 MB
__device__ float g_scores[(size_t)Bq * HH * SS * SS];  // 128 MB
__device__ float g_ctx[NTOK * EE];               // 16 MB
__device__ float g_att[NTOK * EE];               // 16 MB
__device__ float g_h[NTOK * FF];                 // 64 MB
__device__ float g_ff[NTOK * EE];                // 16 MB

// ---------------- helpers ----------------------------------------------------
__device__ __forceinline__ float gelu_f(float v) {
    return 0.5f * v * (1.0f + erff(v * 0.7071067811865476f));
}

// ---------------- embedding: x = tok_emb[seq] * sqrt(E) ----------------------
__global__ void k_embed(const int* __restrict__ seq, const float* __restrict__ tok_emb) {
    int idx = blockIdx.x * blockDim.x + threadIdx.x;
    if (idx < NTOK * EE) {
        int row = idx >> 9;          // /512
        int e   = idx & 511;
        g_x[idx] = tok_emb[seq[row] * EE + e] * 22.62741699796952f;  // sqrt(512)
    }
}

// ---------------- generic GEMM: C[M,N] = A[M,K] @ W[N,K]^T + bias, opt GELU --
// 128x128 block tile, BK=16, 256 threads, 8x8 per-thread tile.
__global__ void __launch_bounds__(256, 2) k_gemm(
    const float* __restrict__ A, const float* __restrict__ W,
    const float* __restrict__ bias, float* __restrict__ C,
    int M, int N, int K, int act)
{
    __shared__ float As[16][128];
    __shared__ float Bs[16][128];
    const int tid = threadIdx.x;
    const int bm = blockIdx.y * 128, bn = blockIdx.x * 128;
    const int tx = tid & 15, ty = tid >> 4;
    const int lr = tid >> 2, lk = (tid & 3) << 2;

    float acc[8][8];
#pragma unroll
    for (int i = 0; i < 8; i++)
#pragma unroll
        for (int j = 0; j < 8; j++) acc[i][j] = 0.0f;

    const float* Ap = A + (size_t)(bm + lr) * K + lk;
    const float* Wp = W + (size_t)(bn + lr) * K + lk;

    for (int kt = 0; kt < K; kt += 16) {
        float4 a0 = *(const float4*)(Ap + kt);
        float4 a1 = *(const float4*)(Ap + (size_t)64 * K + kt);
        float4 b0 = *(const float4*)(Wp + kt);
        float4 b1 = *(const float4*)(Wp + (size_t)64 * K + kt);
        __syncthreads();
        As[lk + 0][lr] = a0.x; As[lk + 1][lr] = a0.y; As[lk + 2][lr] = a0.z; As[lk + 3][lr] = a0.w;
        As[lk + 0][lr + 64] = a1.x; As[lk + 1][lr + 64] = a1.y; As[lk + 2][lr + 64] = a1.z; As[lk + 3][lr + 64] = a1.w;
        Bs[lk + 0][lr] = b0.x; Bs[lk + 1][lr] = b0.y; Bs[lk + 2][lr] = b0.z; Bs[lk + 3][lr] = b0.w;
        Bs[lk + 0][lr + 64] = b1.x; Bs[lk + 1][lr + 64] = b1.y; Bs[lk + 2][lr + 64] = b1.z; Bs[lk + 3][lr + 64] = b1.w;
        __syncthreads();
#pragma unroll
        for (int kk = 0; kk < 16; kk++) {
            float a[8], b[8];
            *(float4*)(a)     = *(const float4*)&As[kk][ty * 8];
            *(float4*)(a + 4) = *(const float4*)&As[kk][ty * 8 + 4];
            *(float4*)(b)     = *(const float4*)&Bs[kk][tx * 8];
            *(float4*)(b + 4) = *(const float4*)&Bs[kk][tx * 8 + 4];
#pragma unroll
            for (int i = 0; i < 8; i++)
#pragma unroll
                for (int j = 0; j < 8; j++)
                    acc[i][j] = fmaf(a[i], b[j], acc[i][j]);
        }
    }
#pragma unroll
    for (int i = 0; i < 8; i++) {
        int row = bm + ty * 8 + i;
#pragma unroll
        for (int j = 0; j < 8; j += 4) {
            int col = bn + tx * 8 + j;
            float4 v;
            v.x = acc[i][j]     + bias[col];
            v.y = acc[i][j + 1] + bias[col + 1];
            v.z = acc[i][j + 2] + bias[col + 2];
            v.w = acc[i][j + 3] + bias[col + 3];
            if (act) { v.x = gelu_f(v.x); v.y = gelu_f(v.y); v.z = gelu_f(v.z); v.w = gelu_f(v.w); }
            *(float4*)(C + (size_t)row * N + col) = v;
        }
    }
}

// ---------------- attention scores: q@k^T*scale + dist bias + pad mask -------
// grid: (S/64 ktiles, S/64 qtiles, B*H). 64x64 output tile per block.
__global__ void __launch_bounds__(256) k_scores(
    const int* __restrict__ seq, const int* __restrict__ squares,
    const float* __restrict__ dist_emb)
{
    const int bh = blockIdx.z, b = bh >> 3, h = bh & 7;
    const int qi0 = blockIdx.y * 64, kj0 = blockIdx.x * 64;
    __shared__ float Qs[64][65];
    __shared__ float Ks[64][65];
    const int tid = threadIdx.x;

    for (int t = tid; t < 1024; t += 256) {      // 1024 float4 per tile
        int r = t >> 4, d4 = (t & 15) << 2;
        float4 q = *(const float4*)(g_qkv + (size_t)(b * SS + qi0 + r) * E3 + h * DH + d4);
        Qs[r][d4] = q.x; Qs[r][d4 + 1] = q.y; Qs[r][d4 + 2] = q.z; Qs[r][d4 + 3] = q.w;
        float4 k = *(const float4*)(g_qkv + (size_t)(b * SS + kj0 + r) * E3 + EE + h * DH + d4);
        Ks[r][d4] = k.x; Ks[r][d4 + 1] = k.y; Ks[r][d4 + 2] = k.z; Ks[r][d4 + 3] = k.w;
    }
    __syncthreads();

    const int tx = tid & 15, ty = tid >> 4;
    float acc[4][4] = {};
#pragma unroll 8
    for (int d = 0; d < 64; d++) {
        float a[4], bb[4];
#pragma unroll
        for (int i = 0; i < 4; i++) a[i] = Qs[ty * 4 + i][d];
#pragma unroll
        for (int j = 0; j < 4; j++) bb[j] = Ks[tx * 4 + j][d];
#pragma unroll
        for (int i = 0; i < 4; i++)
#pragma unroll
            for (int j = 0; j < 4; j++)
                acc[i][j] = fmaf(a[i], bb[j], acc[i][j]);
    }
#pragma unroll
    for (int i = 0; i < 4; i++) {
        int qi = qi0 + ty * 4 + i;
#pragma unroll
        for (int j = 0; j < 4; j++) {
            int kj = kj0 + tx * 4 + j;
            int d = squares[((size_t)b * SS + qi) * SS + kj];
            float v = acc[i][j] * 0.125f + dist_emb[d * HH + h];
            if (seq[b * SS + kj] == 0) v -= 1e9f;
            g_scores[((size_t)bh * SS + qi) * SS + kj] = v;
        }
    }
}

// ---------------- row softmax over S=512 -------------------------------------
__global__ void __launch_bounds__(256) k_softmax()
{
    const int row = blockIdx.x;
    float* p = g_scores + (size_t)row * SS;
    const int tid = threadIdx.x;
    const int lane = tid & 31, wid = tid >> 5;
    __shared__ float redm[8], reds[8];

    float v0 = p[tid], v1 = p[tid + 256];
    float m = fmaxf(v0, v1);
#pragma unroll
    for (int o = 16; o > 0; o >>= 1) m = fmaxf(m, __shfl_xor_sync(0xffffffffu, m, o));
    if (lane == 0) redm[wid] = m;
    __syncthreads();
    m = redm[0];
#pragma unroll
    for (int i = 1; i < 8; i++) m = fmaxf(m, redm[i]);

    float e0 = expf(v0 - m), e1 = expf(v1 - m);
    float s = e0 + e1;
#pragma unroll
    for (int o = 16; o > 0; o >>= 1) s += __shfl_xor_sync(0xffffffffu, s, o);
    if (lane == 0) reds[wid] = s;
    __syncthreads();
    s = reds[0];
#pragma unroll
    for (int i = 1; i < 8; i++) s += reds[i];
    float inv = 1.0f / s;
    p[tid] = e0 * inv;
    p[tid + 256] = e1 * inv;
}

// ---------------- ctx = attn @ v ---------------------------------------------
// grid: (S/64 qtiles, B*H). Each block: 64 query rows x full Dh=64.
__global__ void __launch_bounds__(256) k_ctx()
{
    const int bh = blockIdx.y, b = bh >> 3, h = bh & 7;
    const int qi0 = blockIdx.x * 64;
    __shared__ float At[64][65];
    __shared__ float Vs[64][65];
    const int tid = threadIdx.x, tx = tid & 15, ty = tid >> 4;
    float acc[4][4] = {};

    for (int kt = 0; kt < SS; kt += 64) {
        __syncthreads();
        for (int t = tid; t < 1024; t += 256) {
            int r = t >> 4, c4 = (t & 15) << 2;
            float4 a = *(const float4*)(g_scores + ((size_t)bh * SS + qi0 + r) * SS + kt + c4);
            At[r][c4] = a.x; At[r][c4 + 1] = a.y; At[r][c4 + 2] = a.z; At[r][c4 + 3] = a.w;
            float4 v = *(const float4*)(g_qkv + (size_t)(b * SS + kt + r) * E3 + 2 * EE + h * DH + c4);
            Vs[r][c4] = v.x; Vs[r][c4 + 1] = v.y; Vs[r][c4 + 2] = v.z; Vs[r][c4 + 3] = v.w;
        }
        __syncthreads();
#pragma unroll 8
        for (int j = 0; j < 64; j++) {
            float a[4], vv[4];
#pragma unroll
            for (int i = 0; i < 4; i++) a[i] = At[ty * 4 + i][j];
#pragma unroll
            for (int jj = 0; jj < 4; jj++) vv[jj] = Vs[j][tx * 4 + jj];
#pragma unroll
            for (int i = 0; i < 4; i++)
#pragma unroll
                for (int jj = 0; jj < 4; jj++)
                    acc[i][jj] = fmaf(a[i], vv[jj], acc[i][jj]);
        }
    }
#pragma unroll
    for (int i = 0; i < 4; i++)
#pragma unroll
        for (int jj = 0; jj < 4; jj++)
            g_ctx[(size_t)(b * SS + qi0 + ty * 4 + i) * EE + h * DH + tx * 4 + jj] = acc[i][jj];
}

// ---------------- residual + LayerNorm: out = LN(res + add) ------------------
__global__ void __launch_bounds__(256) k_ln_res(
    const float* __restrict__ res, const float* __restrict__ add,
    const float* __restrict__ w, const float* __restrict__ bb,
    float* __restrict__ out)
{
    const int row = blockIdx.x, tid = threadIdx.x;
    const int lane = tid & 31, wid = tid >> 5;
    __shared__ float r1[8], r2[8];

    size_t base = (size_t)row * EE;
    float v0 = res[base + tid] + add[base + tid];
    float v1 = res[base + tid + 256] + add[base + tid + 256];
    float s = v0 + v1, s2 = v0 * v0 + v1 * v1;
#pragma unroll
    for (int o = 16; o > 0; o >>= 1) {
        s  += __shfl_xor_sync(0xffffffffu, s, o);
        s2 += __shfl_xor_sync(0xffffffffu, s2, o);
    }
    if (lane == 0) { r1[wid] = s; r2[wid] = s2; }
    __syncthreads();
    s = r1[0]; s2 = r2[0];
#pragma unroll
    for (int i = 1; i < 8; i++) { s += r1[i]; s2 += r2[i]; }
    float mean = s * (1.0f / EE);
    float var  = s2 * (1.0f / EE) - mean * mean;
    float inv = rsqrtf(var + 1e-5f);
    out[base + tid]       = (v0 - mean) * inv * w[tid] + bb[tid];
    out[base + tid + 256] = (v1 - mean) * inv * w[tid + 256] + bb[tid + 256];
}

// ---------------- final LN, writes out[(s,b,e)] transposed -------------------
__global__ void __launch_bounds__(256) k_ln_final(
    const float* __restrict__ w, const float* __restrict__ bb,
    float* __restrict__ out)
{
    const int row = blockIdx.x, tid = threadIdx.x;
    const int b = row >> 9, sPos = row & 511;
    const int lane = tid & 31, wid = tid >> 5;
    __shared__ float r1[8], r2[8];

    size_t base = (size_t)row * EE;
    float v0 = g_x[base + tid];
    float v1 = g_x[base + tid + 256];
    float s = v0 + v1, s2 = v0 * v0 + v1 * v1;
#pragma unroll
    for (int o = 16; o > 0; o >>= 1) {
        s  += __shfl_xor_sync(0xffffffffu, s, o);
        s2 += __shfl_xor_sync(0xffffffffu, s2, o);
    }
    if (lane == 0) { r1[wid] = s; r2[wid] = s2; }
    __syncthreads();
    s = r1[0]; s2 = r2[0];
#pragma unroll
    for (int i = 1; i < 8; i++) { s += r1[i]; s2 += r2[i]; }
    float mean = s * (1.0f / EE);
    float var  = s2 * (1.0f / EE) - mean * mean;
    float inv = rsqrtf(var + 1e-5f);
    size_t o = ((size_t)sPos * Bq + b) * EE;
    out[o + tid]       = (v0 - mean) * inv * w[tid] + bb[tid];
    out[o + tid + 256] = (v1 - mean) * inv * w[tid + 256] + bb[tid + 256];
}

// ---------------- key padding mask as float 0/1 ------------------------------
__global__ void k_mask(const int* __restrict__ seq, float* __restrict__ out) {
    int idx = blockIdx.x * blockDim.x + threadIdx.x;
    if (idx < Bq * SS) out[idx] = (seq[idx] == 0) ? 1.0f : 0.0f;
}

// ---------------- launch -----------------------------------------------------
extern "C" void kernel_launch(void* const* d_in, const int* in_sizes, int n_in,
                              void* d_out, int out_size)
{
    const int*   seq       = (const int*)d_in[0];
    const int*   squares   = (const int*)d_in[1];
    const float* tok_emb   = (const float*)d_in[2];
    const float* dist_emb  = (const float*)d_in[3];
    const float* in_proj_w = (const float*)d_in[4];
    const float* in_proj_b = (const float*)d_in[5];
    const float* out_w     = (const float*)d_in[6];
    const float* out_b     = (const float*)d_in[7];
    const float* ff1_w     = (const float*)d_in[8];
    const float* ff1_b     = (const float*)d_in[9];
    const float* ff2_w     = (const float*)d_in[10];
    const float* ff2_b     = (const float*)d_in[11];
    const float* ln1_w     = (const float*)d_in[12];
    const float* ln1_b     = (const float*)d_in[13];
    const float* ln2_w     = (const float*)d_in[14];
    const float* ln2_b     = (const float*)d_in[15];
    const float* lnf_w     = (const float*)d_in[16];
    const float* lnf_b     = (const float*)d_in[17];
    float* out = (float*)d_out;

    float *x, *qkv, *ctx, *att, *hbuf, *ffb;
    cudaGetSymbolAddress((void**)&x,    g_x);
    cudaGetSymbolAddress((void**)&qkv,  g_qkv);
    cudaGetSymbolAddress((void**)&ctx,  g_ctx);
    cudaGetSymbolAddress((void**)&att,  g_att);
    cudaGetSymbolAddress((void**)&hbuf, g_h);
    cudaGetSymbolAddress((void**)&ffb,  g_ff);

    // embedding
    k_embed<<<(NTOK * EE + 255) / 256, 256>>>(seq, tok_emb);

    for (int l = 0; l < LL; l++) {
        // qkv projection: [8192,512] @ [1536,512]^T
        k_gemm<<<dim3(E3 / 128, NTOK / 128), 256>>>(
            x, in_proj_w + (size_t)l * E3 * EE, in_proj_b + (size_t)l * E3,
            qkv, NTOK, E3, EE, 0);
        // attention
        k_scores<<<dim3(SS / 64, SS / 64, Bq * HH), 256>>>(seq, squares, dist_emb);
        k_softmax<<<Bq * HH * SS, 256>>>();
        k_ctx<<<dim3(SS / 64, Bq * HH), 256>>>();
        // out projection
        k_gemm<<<dim3(EE / 128, NTOK / 128), 256>>>(
            ctx, out_w + (size_t)l * EE * EE, out_b + (size_t)l * EE,
            att, NTOK, EE, EE, 0);
        // ln1: x = LN(x + att)
        k_ln_res<<<NTOK, 256>>>(x, att, ln1_w + (size_t)l * EE, ln1_b + (size_t)l * EE, x);
        // ff1 (gelu): [8192,512] @ [2048,512]^T
        k_gemm<<<dim3(FF / 128, NTOK / 128), 256>>>(
            x, ff1_w + (size_t)l * FF * EE, ff1_b + (size_t)l * FF,
            hbuf, NTOK, FF, EE, 1);
        // ff2: [8192,2048] @ [512,2048]^T
        k_gemm<<<dim3(EE / 128, NTOK / 128), 256>>>(
            hbuf, ff2_w + (size_t)l * EE * FF, ff2_b + (size_t)l * EE,
            ffb, NTOK, EE, FF, 0);
        // ln2: x = LN(x + ff)
        k_ln_res<<<NTOK, 256>>>(x, ffb, ln2_w + (size_t)l * EE, ln2_b + (size_t)l * EE, x);
    }

    // final LN + transpose to [S,B,E]
    k_ln_final<<<NTOK, 256>>>(lnf_w, lnf_b, out);

    // key padding mask (if the output buffer includes it)
    if (out_size >= NTOK * EE + Bq * SS) {
        k_mask<<<(Bq * SS + 255) / 256, 256>>>(seq, out + (size_t)NTOK * EE);
    }
}

// round 4
// speedup vs baseline: 1.8934x; 1.8934x over previous
#include <cuda_runtime.h>
#include <cuda_bf16.h>
#include <math.h>
#include <stdint.h>

// Problem constants
#define Bq   16
#define SS   512
#define EE   512
#define HH   8
#define FF   2048
#define LL   6
#define DH   64
#define NTOK (Bq * SS)           // 8192 tokens
#define E3   (3 * EE)            // 1536

// ---------------- scratch (device globals; no runtime allocation) ------------
__device__ float g_x[NTOK * EE];                       // fp32 residual stream
__device__ float g_qkv[NTOK * E3];
__device__ float g_scores[(size_t)Bq * HH * SS * SS];  // 128 MB
__device__ float g_att[NTOK * EE];
__device__ float g_ff[NTOK * EE];

// split-bf16 activations
__device__ __nv_bfloat16 g_xh[NTOK * EE],  g_xl[NTOK * EE];
__device__ __nv_bfloat16 g_cxh[NTOK * EE], g_cxl[NTOK * EE];
__device__ __nv_bfloat16 g_hh[NTOK * FF],  g_hl[NTOK * FF];

// split-bf16 weights
__device__ __nv_bfloat16 g_wqh[LL * E3 * EE], g_wql[LL * E3 * EE];
__device__ __nv_bfloat16 g_woh[LL * EE * EE], g_wol[LL * EE * EE];
__device__ __nv_bfloat16 g_f1h[LL * FF * EE], g_f1l[LL * FF * EE];
__device__ __nv_bfloat16 g_f2h[LL * EE * FF], g_f2l[LL * EE * FF];

// ---------------- low-level helpers ------------------------------------------
__device__ __forceinline__ uint32_t smem_u32(const void* p) {
    uint32_t a;
    asm("{ .reg .u64 t; cvta.to.shared.u64 t, %1; cvt.u32.u64 %0, t; }" : "=r"(a) : "l"(p));
    return a;
}
__device__ __forceinline__ void cp16(uint32_t dst, const void* src) {
    asm volatile("cp.async.ca.shared.global [%0], [%1], 16;" :: "r"(dst), "l"(src) : "memory");
}
__device__ __forceinline__ void cp_commit() { asm volatile("cp.async.commit_group;" ::: "memory"); }
template <int N>
__device__ __forceinline__ void cp_wait() { asm volatile("cp.async.wait_group %0;" :: "n"(N) : "memory"); }

__device__ __forceinline__ void ldsm4(uint32_t* r, uint32_t addr) {
    asm volatile("ldmatrix.sync.aligned.m8n8.x4.shared.b16 {%0,%1,%2,%3}, [%4];"
        : "=r"(r[0]), "=r"(r[1]), "=r"(r[2]), "=r"(r[3]) : "r"(addr));
}
__device__ __forceinline__ void mma16816(float* c, const uint32_t* a, const uint32_t* b) {
    asm volatile(
        "mma.sync.aligned.m16n8k16.row.col.f32.bf16.bf16.f32 "
        "{%0,%1,%2,%3}, {%4,%5,%6,%7}, {%8,%9}, {%0,%1,%2,%3};"
        : "+f"(c[0]), "+f"(c[1]), "+f"(c[2]), "+f"(c[3])
        : "r"(a[0]), "r"(a[1]), "r"(a[2]), "r"(a[3]), "r"(b[0]), "r"(b[1]));
}

__device__ __forceinline__ float gelu_f(float v) {
    return 0.5f * v * (1.0f + erff(v * 0.7071067811865476f));
}
__device__ __forceinline__ void split2(float v, __nv_bfloat16& h, __nv_bfloat16& l) {
    h = __float2bfloat16(v);
    l = __float2bfloat16(v - __bfloat162float(h));
}

// ---------------- weight splitting -------------------------------------------
__global__ void k_split(const float* __restrict__ s, __nv_bfloat16* __restrict__ hi,
                        __nv_bfloat16* __restrict__ lo, int n) {
    int i = blockIdx.x * blockDim.x + threadIdx.x;
    if (i < n) { __nv_bfloat16 h, l; split2(s[i], h, l); hi[i] = h; lo[i] = l; }
}

// ---------------- embedding --------------------------------------------------
__global__ void k_embed(const int* __restrict__ seq, const float* __restrict__ tok_emb) {
    int idx = blockIdx.x * blockDim.x + threadIdx.x;
    if (idx < NTOK * EE) {
        int row = idx >> 9, e = idx & 511;
        float v = tok_emb[seq[row] * EE + e] * 22.62741699796952f;
        g_x[idx] = v;
        __nv_bfloat16 h, l; split2(v, h, l);
        g_xh[idx] = h; g_xl[idx] = l;
    }
}

// ---------------- mma.sync split-bf16 GEMM -----------------------------------
// C[M,N] = A[M,K] @ W[N,K]^T + bias.  CTA 128x128, BK=64, 8 warps (64x32 each),
// double-buffered cp.async stages.  3 mma passes: AhBh + AhBl + AlBh.
// Stage layout (64KB): Ah @0, Al @16K, Bh @32K, Bl @48K; rows of 128B, XOR swz.
#define STAGEB 65536
#define GSMEM  (2 * STAGEB)

__global__ void __launch_bounds__(256, 1) k_mmagemm(
    const __nv_bfloat16* __restrict__ Ah, const __nv_bfloat16* __restrict__ Al,
    const __nv_bfloat16* __restrict__ Wh, const __nv_bfloat16* __restrict__ Wl,
    const float* __restrict__ bias,
    float* __restrict__ Cf,
    __nv_bfloat16* __restrict__ Chh, __nv_bfloat16* __restrict__ Cll,
    int N, int K, int act)
{
    extern __shared__ char smem[];
    const uint32_t sb = smem_u32(smem);
    const int tid = threadIdx.x, wid = tid >> 5, lane = tid & 31;
    const int bm = blockIdx.y * 128, bn = blockIdx.x * 128;
    const int m0 = (wid >> 2) * 64, n0 = (wid & 3) * 32;

    // ldmatrix per-lane address components
    const int subA = lane >> 3;
    const int arow = ((subA & 1) << 3) + (lane & 7);   // row offset within 16-row tile
    const int achk = subA >> 1;                        // k-chunk offset (0/1)
    const int brow = ((subA >> 1) << 3) + (lane & 7);  // row offset within 16-n group
    const int bchk = subA & 1;

    float acc[4][4][4];
#pragma unroll
    for (int i = 0; i < 4; i++)
#pragma unroll
        for (int j = 0; j < 4; j++)
#pragma unroll
            for (int q = 0; q < 4; q++) acc[i][j][q] = 0.0f;

    const int KI = K >> 6;

    // stage loader: 4096 x 16B chunks
    auto load_stage = [&](int kt) {
        const uint32_t bs = sb + (kt & 1) * STAGEB;
        const int kcol = kt << 6;
#pragma unroll
        for (int p = 0; p < 16; p++) {
            int t = tid + (p << 8);           // 0..4095
            int tile = t >> 10;               // 0..3
            int q = t & 1023;
            int r = q >> 3, c16 = q & 7;
            uint32_t dst = bs + tile * 16384 + r * 128 + (((uint32_t)(c16 ^ (r & 7))) << 4);
            const __nv_bfloat16* src;
            if (tile == 0)      src = Ah + (size_t)(bm + r) * K + kcol + c16 * 8;
            else if (tile == 1) src = Al + (size_t)(bm + r) * K + kcol + c16 * 8;
            else if (tile == 2) src = Wh + (size_t)(bn + r) * K + kcol + c16 * 8;
            else                src = Wl + (size_t)(bn + r) * K + kcol + c16 * 8;
            cp16(dst, src);
        }
        cp_commit();
    };

    load_stage(0);
    for (int kt = 0; kt < KI; kt++) {
        if (kt + 1 < KI) { load_stage(kt + 1); cp_wait<1>(); }
        else             { cp_wait<0>(); }
        __syncthreads();

        const uint32_t bs = sb + (kt & 1) * STAGEB;
#pragma unroll
        for (int ks = 0; ks < 4; ks++) {
            uint32_t ah[4][4], al[4][4];
#pragma unroll
            for (int mi = 0; mi < 4; mi++) {
                int r = m0 + mi * 16 + arow;
                int ck = ks * 2 + achk;
                uint32_t ad = bs + r * 128 + (((uint32_t)(ck ^ (r & 7))) << 4);
                ldsm4(ah[mi], ad);
                ldsm4(al[mi], ad + 16384);
            }
            uint32_t bh[4][2], bl[4][2];
#pragma unroll
            for (int nh = 0; nh < 2; nh++) {
                int r = n0 + nh * 16 + brow;
                int ck = ks * 2 + bchk;
                uint32_t bd = bs + 32768 + r * 128 + (((uint32_t)(ck ^ (r & 7))) << 4);
                uint32_t q[4];
                ldsm4(q, bd);
                bh[nh * 2][0] = q[0]; bh[nh * 2][1] = q[1];
                bh[nh * 2 + 1][0] = q[2]; bh[nh * 2 + 1][1] = q[3];
                ldsm4(q, bd + 16384);
                bl[nh * 2][0] = q[0]; bl[nh * 2][1] = q[1];
                bl[nh * 2 + 1][0] = q[2]; bl[nh * 2 + 1][1] = q[3];
            }
#pragma unroll
            for (int mi = 0; mi < 4; mi++)
#pragma unroll
                for (int nc = 0; nc < 4; nc++) {
                    mma16816(acc[mi][nc], ah[mi], bh[nc]);
                    mma16816(acc[mi][nc], ah[mi], bl[nc]);
                    mma16816(acc[mi][nc], al[mi], bh[nc]);
                }
        }
        __syncthreads();
    }

    // epilogue
    const int g = lane >> 2, tq = lane & 3;
#pragma unroll
    for (int mi = 0; mi < 4; mi++) {
#pragma unroll
        for (int nc = 0; nc < 4; nc++) {
            int row0 = bm + m0 + mi * 16 + g;
            int col  = bn + n0 + nc * 8 + tq * 2;
            float b0 = bias[col], b1 = bias[col + 1];
            float v0 = acc[mi][nc][0] + b0, v1 = acc[mi][nc][1] + b1;
            float v2 = acc[mi][nc][2] + b0, v3 = acc[mi][nc][3] + b1;
            if (act) { v0 = gelu_f(v0); v1 = gelu_f(v1); v2 = gelu_f(v2); v3 = gelu_f(v3); }
            if (Cf) {
                *(float2*)(Cf + (size_t)row0 * N + col)       = make_float2(v0, v1);
                *(float2*)(Cf + (size_t)(row0 + 8) * N + col) = make_float2(v2, v3);
            } else {
                __nv_bfloat16 h0, l0, h1, l1;
                split2(v0, h0, l0); split2(v1, h1, l1);
                *(__nv_bfloat162*)(Chh + (size_t)row0 * N + col) = __nv_bfloat162(h0, h1);
                *(__nv_bfloat162*)(Cll + (size_t)row0 * N + col) = __nv_bfloat162(l0, l1);
                split2(v2, h0, l0); split2(v3, h1, l1);
                *(__nv_bfloat162*)(Chh + (size_t)(row0 + 8) * N + col) = __nv_bfloat162(h0, h1);
                *(__nv_bfloat162*)(Cll + (size_t)(row0 + 8) * N + col) = __nv_bfloat162(l0, l1);
            }
        }
    }
}

// ---------------- attention scores (fp32) ------------------------------------
__global__ void __launch_bounds__(256) k_scores(
    const int* __restrict__ seq, const int* __restrict__ squares,
    const float* __restrict__ dist_emb)
{
    const int bh = blockIdx.z, b = bh >> 3, h = bh & 7;
    const int qi0 = blockIdx.y * 64, kj0 = blockIdx.x * 64;
    __shared__ float Qs[64][65];
    __shared__ float Ks[64][65];
    const int tid = threadIdx.x;

    for (int t = tid; t < 1024; t += 256) {
        int r = t >> 4, d4 = (t & 15) << 2;
        float4 q = *(const float4*)(g_qkv + (size_t)(b * SS + qi0 + r) * E3 + h * DH + d4);
        Qs[r][d4] = q.x; Qs[r][d4 + 1] = q.y; Qs[r][d4 + 2] = q.z; Qs[r][d4 + 3] = q.w;
        float4 k = *(const float4*)(g_qkv + (size_t)(b * SS + kj0 + r) * E3 + EE + h * DH + d4);
        Ks[r][d4] = k.x; Ks[r][d4 + 1] = k.y; Ks[r][d4 + 2] = k.z; Ks[r][d4 + 3] = k.w;
    }
    __syncthreads();

    const int tx = tid & 15, ty = tid >> 4;
    float acc[4][4] = {};
#pragma unroll 8
    for (int d = 0; d < 64; d++) {
        float a[4], bb[4];
#pragma unroll
        for (int i = 0; i < 4; i++) a[i] = Qs[ty * 4 + i][d];
#pragma unroll
        for (int j = 0; j < 4; j++) bb[j] = Ks[tx * 4 + j][d];
#pragma unroll
        for (int i = 0; i < 4; i++)
#pragma unroll
            for (int j = 0; j < 4; j++)
                acc[i][j] = fmaf(a[i], bb[j], acc[i][j]);
    }
#pragma unroll
    for (int i = 0; i < 4; i++) {
        int qi = qi0 + ty * 4 + i;
#pragma unroll
        for (int j = 0; j < 4; j++) {
            int kj = kj0 + tx * 4 + j;
            int d = squares[((size_t)b * SS + qi) * SS + kj];
            float v = acc[i][j] * 0.125f + dist_emb[d * HH + h];
            if (seq[b * SS + kj] == 0) v -= 1e9f;
            g_scores[((size_t)bh * SS + qi) * SS + kj] = v;
        }
    }
}

// ---------------- row softmax -------------------------------------------------
__global__ void __launch_bounds__(256) k_softmax()
{
    const int row = blockIdx.x;
    float* p = g_scores + (size_t)row * SS;
    const int tid = threadIdx.x;
    const int lane = tid & 31, wid = tid >> 5;
    __shared__ float redm[8], reds[8];

    float v0 = p[tid], v1 = p[tid + 256];
    float m = fmaxf(v0, v1);
#pragma unroll
    for (int o = 16; o > 0; o >>= 1) m = fmaxf(m, __shfl_xor_sync(0xffffffffu, m, o));
    if (lane == 0) redm[wid] = m;
    __syncthreads();
    m = redm[0];
#pragma unroll
    for (int i = 1; i < 8; i++) m = fmaxf(m, redm[i]);

    float e0 = expf(v0 - m), e1 = expf(v1 - m);
    float s = e0 + e1;
#pragma unroll
    for (int o = 16; o > 0; o >>= 1) s += __shfl_xor_sync(0xffffffffu, s, o);
    if (lane == 0) reds[wid] = s;
    __syncthreads();
    s = reds[0];
#pragma unroll
    for (int i = 1; i < 8; i++) s += reds[i];
    float inv = 1.0f / s;
    p[tid] = e0 * inv;
    p[tid + 256] = e1 * inv;
}

// ---------------- ctx = attn @ v, emits bf16 hi/lo ---------------------------
__global__ void __launch_bounds__(256) k_ctx()
{
    const int bh = blockIdx.y, b = bh >> 3, hd = bh & 7;
    const int qi0 = blockIdx.x * 64;
    __shared__ float At[64][65];
    __shared__ float Vs[64][65];
    const int tid = threadIdx.x, tx = tid & 15, ty = tid >> 4;
    float acc[4][4] = {};

    for (int kt = 0; kt < SS; kt += 64) {
        __syncthreads();
        for (int t = tid; t < 1024; t += 256) {
            int r = t >> 4, c4 = (t & 15) << 2;
            float4 a = *(const float4*)(g_scores + ((size_t)bh * SS + qi0 + r) * SS + kt + c4);
            At[r][c4] = a.x; At[r][c4 + 1] = a.y; At[r][c4 + 2] = a.z; At[r][c4 + 3] = a.w;
            float4 v = *(const float4*)(g_qkv + (size_t)(b * SS + kt + r) * E3 + 2 * EE + hd * DH + c4);
            Vs[r][c4] = v.x; Vs[r][c4 + 1] = v.y; Vs[r][c4 + 2] = v.z; Vs[r][c4 + 3] = v.w;
        }
        __syncthreads();
#pragma unroll 8
        for (int j = 0; j < 64; j++) {
            float a[4], vv[4];
#pragma unroll
            for (int i = 0; i < 4; i++) a[i] = At[ty * 4 + i][j];
#pragma unroll
            for (int jj = 0; jj < 4; jj++) vv[jj] = Vs[j][tx * 4 + jj];
#pragma unroll
            for (int i = 0; i < 4; i++)
#pragma unroll
                for (int jj = 0; jj < 4; jj++)
                    acc[i][jj] = fmaf(a[i], vv[jj], acc[i][jj]);
        }
    }
#pragma unroll
    for (int i = 0; i < 4; i++)
#pragma unroll
        for (int jj = 0; jj < 4; jj++) {
            size_t idx = (size_t)(b * SS + qi0 + ty * 4 + i) * EE + hd * DH + tx * 4 + jj;
            __nv_bfloat16 h16, l16; split2(acc[i][jj], h16, l16);
            g_cxh[idx] = h16; g_cxl[idx] = l16;
        }
}

// ---------------- residual + LayerNorm, fp32 + bf16 hi/lo --------------------
__global__ void __launch_bounds__(256) k_ln_res(
    const float* __restrict__ res, const float* __restrict__ add,
    const float* __restrict__ w, const float* __restrict__ bb,
    float* __restrict__ out)
{
    const int row = blockIdx.x, tid = threadIdx.x;
    const int lane = tid & 31, wid = tid >> 5;
    __shared__ float r1[8], r2[8];

    size_t base = (size_t)row * EE;
    float v0 = res[base + tid] + add[base + tid];
    float v1 = res[base + tid + 256] + add[base + tid + 256];
    float s = v0 + v1, s2 = v0 * v0 + v1 * v1;
#pragma unroll
    for (int o = 16; o > 0; o >>= 1) {
        s  += __shfl_xor_sync(0xffffffffu, s, o);
        s2 += __shfl_xor_sync(0xffffffffu, s2, o);
    }
    if (lane == 0) { r1[wid] = s; r2[wid] = s2; }
    __syncthreads();
    s = r1[0]; s2 = r2[0];
#pragma unroll
    for (int i = 1; i < 8; i++) { s += r1[i]; s2 += r2[i]; }
    float mean = s * (1.0f / EE);
    float var  = s2 * (1.0f / EE) - mean * mean;
    float inv = rsqrtf(var + 1e-5f);
    float o0 = (v0 - mean) * inv * w[tid] + bb[tid];
    float o1 = (v1 - mean) * inv * w[tid + 256] + bb[tid + 256];
    out[base + tid] = o0;
    out[base + tid + 256] = o1;
    __nv_bfloat16 h16, l16;
    split2(o0, h16, l16); g_xh[base + tid] = h16;       g_xl[base + tid] = l16;
    split2(o1, h16, l16); g_xh[base + tid + 256] = h16; g_xl[base + tid + 256] = l16;
}

// ---------------- final LN -> out[(s,b,e)] -----------------------------------
__global__ void __launch_bounds__(256) k_ln_final(
    const float* __restrict__ w, const float* __restrict__ bb,
    float* __restrict__ out)
{
    const int row = blockIdx.x, tid = threadIdx.x;
    const int b = row >> 9, sPos = row & 511;
    const int lane = tid & 31, wid = tid >> 5;
    __shared__ float r1[8], r2[8];

    size_t base = (size_t)row * EE;
    float v0 = g_x[base + tid];
    float v1 = g_x[base + tid + 256];
    float s = v0 + v1, s2 = v0 * v0 + v1 * v1;
#pragma unroll
    for (int o = 16; o > 0; o >>= 1) {
        s  += __shfl_xor_sync(0xffffffffu, s, o);
        s2 += __shfl_xor_sync(0xffffffffu, s2, o);
    }
    if (lane == 0) { r1[wid] = s; r2[wid] = s2; }
    __syncthreads();
    s = r1[0]; s2 = r2[0];
#pragma unroll
    for (int i = 1; i < 8; i++) { s += r1[i]; s2 += r2[i]; }
    float mean = s * (1.0f / EE);
    float var  = s2 * (1.0f / EE) - mean * mean;
    float inv = rsqrtf(var + 1e-5f);
    size_t o = ((size_t)sPos * Bq + b) * EE;
    out[o + tid]       = (v0 - mean) * inv * w[tid] + bb[tid];
    out[o + tid + 256] = (v1 - mean) * inv * w[tid + 256] + bb[tid + 256];
}

// ---------------- key padding mask -------------------------------------------
__global__ void k_mask(const int* __restrict__ seq, float* __restrict__ out) {
    int idx = blockIdx.x * blockDim.x + threadIdx.x;
    if (idx < Bq * SS) out[idx] = (seq[idx] == 0) ? 1.0f : 0.0f;
}

// ---------------- launch -----------------------------------------------------
extern "C" void kernel_launch(void* const* d_in, const int* in_sizes, int n_in,
                              void* d_out, int out_size)
{
    const int*   seq       = (const int*)d_in[0];
    const int*   squares   = (const int*)d_in[1];
    const float* tok_emb   = (const float*)d_in[2];
    const float* dist_emb  = (const float*)d_in[3];
    const float* in_proj_w = (const float*)d_in[4];
    const float* in_proj_b = (const float*)d_in[5];
    const float* out_w     = (const float*)d_in[6];
    const float* out_b     = (const float*)d_in[7];
    const float* ff1_w     = (const float*)d_in[8];
    const float* ff1_b     = (const float*)d_in[9];
    const float* ff2_w     = (const float*)d_in[10];
    const float* ff2_b     = (const float*)d_in[11];
    const float* ln1_w     = (const float*)d_in[12];
    const float* ln1_b     = (const float*)d_in[13];
    const float* ln2_w     = (const float*)d_in[14];
    const float* ln2_b     = (const float*)d_in[15];
    const float* lnf_w     = (const float*)d_in[16];
    const float* lnf_b     = (const float*)d_in[17];
    float* out = (float*)d_out;

    float *x, *qkv, *att, *ffb;
    cudaGetSymbolAddress((void**)&x,   g_x);
    cudaGetSymbolAddress((void**)&qkv, g_qkv);
    cudaGetSymbolAddress((void**)&att, g_att);
    cudaGetSymbolAddress((void**)&ffb, g_ff);
    __nv_bfloat16 *xh, *xl, *cxh, *cxl, *hh, *hl;
    __nv_bfloat16 *wqh, *wql, *woh, *wol, *f1h, *f1l, *f2h, *f2l;
    cudaGetSymbolAddress((void**)&xh,  g_xh);  cudaGetSymbolAddress((void**)&xl,  g_xl);
    cudaGetSymbolAddress((void**)&cxh, g_cxh); cudaGetSymbolAddress((void**)&cxl, g_cxl);
    cudaGetSymbolAddress((void**)&hh,  g_hh);  cudaGetSymbolAddress((void**)&hl,  g_hl);
    cudaGetSymbolAddress((void**)&wqh, g_wqh); cudaGetSymbolAddress((void**)&wql, g_wql);
    cudaGetSymbolAddress((void**)&woh, g_woh); cudaGetSymbolAddress((void**)&wol, g_wol);
    cudaGetSymbolAddress((void**)&f1h, g_f1h); cudaGetSymbolAddress((void**)&f1l, g_f1l);
    cudaGetSymbolAddress((void**)&f2h, g_f2h); cudaGetSymbolAddress((void**)&f2l, g_f2l);

    cudaFuncSetAttribute(k_mmagemm, cudaFuncAttributeMaxDynamicSharedMemorySize, GSMEM);

    // split weights
    { int n = LL * E3 * EE; k_split<<<(n + 255) / 256, 256>>>(in_proj_w, wqh, wql, n); }
    { int n = LL * EE * EE; k_split<<<(n + 255) / 256, 256>>>(out_w, woh, wol, n); }
    { int n = LL * FF * EE; k_split<<<(n + 255) / 256, 256>>>(ff1_w, f1h, f1l, n); }
    { int n = LL * EE * FF; k_split<<<(n + 255) / 256, 256>>>(ff2_w, f2h, f2l, n); }

    // embedding
    k_embed<<<(NTOK * EE + 255) / 256, 256>>>(seq, tok_emb);

    for (int l = 0; l < LL; l++) {
        // qkv projection
        k_mmagemm<<<dim3(E3 / 128, NTOK / 128), 256, GSMEM>>>(
            xh, xl, wqh + (size_t)l * E3 * EE, wql + (size_t)l * E3 * EE,
            in_proj_b + (size_t)l * E3, qkv, nullptr, nullptr, E3, EE, 0);
        // attention (fp32)
        k_scores<<<dim3(SS / 64, SS / 64, Bq * HH), 256>>>(seq, squares, dist_emb);
        k_softmax<<<Bq * HH * SS, 256>>>();
        k_ctx<<<dim3(SS / 64, Bq * HH), 256>>>();
        // out projection
        k_mmagemm<<<dim3(EE / 128, NTOK / 128), 256, GSMEM>>>(
            cxh, cxl, woh + (size_t)l * EE * EE, wol + (size_t)l * EE * EE,
            out_b + (size_t)l * EE, att, nullptr, nullptr, EE, EE, 0);
        // ln1
        k_ln_res<<<NTOK, 256>>>(x, att, ln1_w + (size_t)l * EE, ln1_b + (size_t)l * EE, x);
        // ff1 + gelu (bf16 hi/lo out)
        k_mmagemm<<<dim3(FF / 128, NTOK / 128), 256, GSMEM>>>(
            xh, xl, f1h + (size_t)l * FF * EE, f1l + (size_t)l * FF * EE,
            ff1_b + (size_t)l * FF, nullptr, hh, hl, FF, EE, 1);
        // ff2
        k_mmagemm<<<dim3(EE / 128, NTOK / 128), 256, GSMEM>>>(
            hh, hl, f2h + (size_t)l * EE * FF, f2l + (size_t)l * EE * FF,
            ff2_b + (size_t)l * EE, ffb, nullptr, nullptr, EE, FF, 0);
        // ln2
        k_ln_res<<<NTOK, 256>>>(x, ffb, ln2_w + (size_t)l * EE, ln2_b + (size_t)l * EE, x);
    }

    // final LN + transpose to [S,B,E]
    k_ln_final<<<NTOK, 256>>>(lnf_w, lnf_b, out);

    if (out_size >= NTOK * EE + Bq * SS) {
        k_mask<<<(Bq * SS + 255) / 256, 256>>>(seq, out + (size_t)NTOK * EE);
    }
}

// round 8
// speedup vs baseline: 2.6914x; 1.4215x over previous
#include <cuda_runtime.h>
#include <cuda_bf16.h>
#include <math.h>
#include <stdint.h>

// Problem constants
#define Bq   16
#define SS   512
#define EE   512
#define HH   8
#define FF   2048
#define LL   6
#define DH   64
#define NTOK (Bq * SS)           // 8192 tokens
#define E3   (3 * EE)            // 1536

// ---------------- scratch (device globals; no runtime allocation) ------------
__device__ float g_x[NTOK * EE];                       // fp32 residual stream
__device__ float g_att[NTOK * EE];
__device__ float g_ff[NTOK * EE];

// split-bf16 activations
__device__ __nv_bfloat16 g_xh[NTOK * EE],  g_xl[NTOK * EE];
__device__ __nv_bfloat16 g_cxh[NTOK * EE], g_cxl[NTOK * EE];
__device__ __nv_bfloat16 g_hh[NTOK * FF],  g_hl[NTOK * FF];
__device__ __nv_bfloat16 g_qkvh[NTOK * E3], g_qkvl[NTOK * E3];

// split-bf16 weights
__device__ __nv_bfloat16 g_wqh[LL * E3 * EE], g_wql[LL * E3 * EE];
__device__ __nv_bfloat16 g_woh[LL * EE * EE], g_wol[LL * EE * EE];
__device__ __nv_bfloat16 g_f1h[LL * FF * EE], g_f1l[LL * FF * EE];
__device__ __nv_bfloat16 g_f2h[LL * EE * FF], g_f2l[LL * EE * FF];

// ---------------- low-level helpers ------------------------------------------
__device__ __forceinline__ uint32_t smem_u32(const void* p) {
    uint32_t a;
    asm("{ .reg .u64 t; cvta.to.shared.u64 t, %1; cvt.u32.u64 %0, t; }" : "=r"(a) : "l"(p));
    return a;
}
__device__ __forceinline__ void cp16(uint32_t dst, const void* src) {
    asm volatile("cp.async.ca.shared.global [%0], [%1], 16;" :: "r"(dst), "l"(src) : "memory");
}
__device__ __forceinline__ void cp_commit() { asm volatile("cp.async.commit_group;" ::: "memory"); }
template <int N>
__device__ __forceinline__ void cp_wait() { asm volatile("cp.async.wait_group %0;" :: "n"(N) : "memory"); }

__device__ __forceinline__ void ldsm4(uint32_t* r, uint32_t addr) {
    asm volatile("ldmatrix.sync.aligned.m8n8.x4.shared.b16 {%0,%1,%2,%3}, [%4];"
        : "=r"(r[0]), "=r"(r[1]), "=r"(r[2]), "=r"(r[3]) : "r"(addr));
}
__device__ __forceinline__ void ldsm4t(uint32_t* r, uint32_t addr) {
    asm volatile("ldmatrix.sync.aligned.m8n8.x4.trans.shared.b16 {%0,%1,%2,%3}, [%4];"
        : "=r"(r[0]), "=r"(r[1]), "=r"(r[2]), "=r"(r[3]) : "r"(addr));
}
__device__ __forceinline__ void mma16816(float* c, const uint32_t* a, const uint32_t* b) {
    asm volatile(
        "mma.sync.aligned.m16n8k16.row.col.f32.bf16.bf16.f32 "
        "{%0,%1,%2,%3}, {%4,%5,%6,%7}, {%8,%9}, {%0,%1,%2,%3};"
        : "+f"(c[0]), "+f"(c[1]), "+f"(c[2]), "+f"(c[3])
        : "r"(a[0]), "r"(a[1]), "r"(a[2]), "r"(a[3]), "r"(b[0]), "r"(b[1]));
}

__device__ __forceinline__ float gelu_f(float v) {
    return 0.5f * v * (1.0f + erff(v * 0.7071067811865476f));
}
__device__ __forceinline__ void split2(float v, __nv_bfloat16& h, __nv_bfloat16& l) {
    h = __float2bfloat16(v);
    l = __float2bfloat16(v - __bfloat162float(h));
}
__device__ __forceinline__ uint32_t packbf2(float a, float b) {
    __nv_bfloat162 t = __floats2bfloat162_rn(a, b);
    return *(uint32_t*)&t;
}

// ---------------- weight splitting -------------------------------------------
__global__ void k_split(const float* __restrict__ s, __nv_bfloat16* __restrict__ hi,
                        __nv_bfloat16* __restrict__ lo, int n) {
    int i = blockIdx.x * blockDim.x + threadIdx.x;
    if (i < n) { __nv_bfloat16 h, l; split2(s[i], h, l); hi[i] = h; lo[i] = l; }
}

// ---------------- embedding --------------------------------------------------
__global__ void k_embed(const int* __restrict__ seq, const float* __restrict__ tok_emb) {
    int idx = blockIdx.x * blockDim.x + threadIdx.x;
    if (idx < NTOK * EE) {
        int row = idx >> 9, e = idx & 511;
        float v = tok_emb[seq[row] * EE + e] * 22.62741699796952f;
        g_x[idx] = v;
        __nv_bfloat16 h, l; split2(v, h, l);
        g_xh[idx] = h; g_xl[idx] = l;
    }
}

// ---------------- mma.sync split-bf16 GEMM -----------------------------------
// C[M,N] = A[M,K] @ W[N,K]^T + bias.  CTA 128x128, BK=64, 8 warps (64x32 each),
// double-buffered cp.async stages.  3 mma passes: AhBh + AhBl + AlBh.
#define STAGEB 65536
#define GSMEM  (2 * STAGEB)

__global__ void __launch_bounds__(256, 1) k_mmagemm(
    const __nv_bfloat16* __restrict__ Ah, const __nv_bfloat16* __restrict__ Al,
    const __nv_bfloat16* __restrict__ Wh, const __nv_bfloat16* __restrict__ Wl,
    const float* __restrict__ bias,
    float* __restrict__ Cf,
    __nv_bfloat16* __restrict__ Chh, __nv_bfloat16* __restrict__ Cll,
    int N, int K, int act)
{
    extern __shared__ char smem[];
    const uint32_t sb = smem_u32(smem);
    const int tid = threadIdx.x, wid = tid >> 5, lane = tid & 31;
    const int bm = blockIdx.y * 128, bn = blockIdx.x * 128;
    const int m0 = (wid >> 2) * 64, n0 = (wid & 3) * 32;

    const int subA = lane >> 3;
    const int arow = ((subA & 1) << 3) + (lane & 7);
    const int achk = subA >> 1;
    const int brow = ((subA >> 1) << 3) + (lane & 7);
    const int bchk = subA & 1;

    float acc[4][4][4];
#pragma unroll
    for (int i = 0; i < 4; i++)
#pragma unroll
        for (int j = 0; j < 4; j++)
#pragma unroll
            for (int q = 0; q < 4; q++) acc[i][j][q] = 0.0f;

    const int KI = K >> 6;

    auto load_stage = [&](int kt) {
        const uint32_t bs = sb + (kt & 1) * STAGEB;
        const int kcol = kt << 6;
#pragma unroll
        for (int p = 0; p < 16; p++) {
            int t = tid + (p << 8);
            int tile = t >> 10;
            int q = t & 1023;
            int r = q >> 3, c16 = q & 7;
            uint32_t dst = bs + tile * 16384 + r * 128 + (((uint32_t)(c16 ^ (r & 7))) << 4);
            const __nv_bfloat16* src;
            if (tile == 0)      src = Ah + (size_t)(bm + r) * K + kcol + c16 * 8;
            else if (tile == 1) src = Al + (size_t)(bm + r) * K + kcol + c16 * 8;
            else if (tile == 2) src = Wh + (size_t)(bn + r) * K + kcol + c16 * 8;
            else                src = Wl + (size_t)(bn + r) * K + kcol + c16 * 8;
            cp16(dst, src);
        }
        cp_commit();
    };

    load_stage(0);
    for (int kt = 0; kt < KI; kt++) {
        if (kt + 1 < KI) { load_stage(kt + 1); cp_wait<1>(); }
        else             { cp_wait<0>(); }
        __syncthreads();

        const uint32_t bs = sb + (kt & 1) * STAGEB;
#pragma unroll
        for (int ks = 0; ks < 4; ks++) {
            uint32_t ah[4][4], al[4][4];
#pragma unroll
            for (int mi = 0; mi < 4; mi++) {
                int r = m0 + mi * 16 + arow;
                int ck = ks * 2 + achk;
                uint32_t ad = bs + r * 128 + (((uint32_t)(ck ^ (r & 7))) << 4);
                ldsm4(ah[mi], ad);
                ldsm4(al[mi], ad + 16384);
            }
            uint32_t bh[4][2], bl[4][2];
#pragma unroll
            for (int nh = 0; nh < 2; nh++) {
                int r = n0 + nh * 16 + brow;
                int ck = ks * 2 + bchk;
                uint32_t bd = bs + 32768 + r * 128 + (((uint32_t)(ck ^ (r & 7))) << 4);
                uint32_t q[4];
                ldsm4(q, bd);
                bh[nh * 2][0] = q[0]; bh[nh * 2][1] = q[1];
                bh[nh * 2 + 1][0] = q[2]; bh[nh * 2 + 1][1] = q[3];
                ldsm4(q, bd + 16384);
                bl[nh * 2][0] = q[0]; bl[nh * 2][1] = q[1];
                bl[nh * 2 + 1][0] = q[2]; bl[nh * 2 + 1][1] = q[3];
            }
#pragma unroll
            for (int mi = 0; mi < 4; mi++)
#pragma unroll
                for (int nc = 0; nc < 4; nc++) {
                    mma16816(acc[mi][nc], ah[mi], bh[nc]);
                    mma16816(acc[mi][nc], ah[mi], bl[nc]);
                    mma16816(acc[mi][nc], al[mi], bh[nc]);
                }
        }
        __syncthreads();
    }

    const int g = lane >> 2, tq = lane & 3;
#pragma unroll
    for (int mi = 0; mi < 4; mi++) {
#pragma unroll
        for (int nc = 0; nc < 4; nc++) {
            int row0 = bm + m0 + mi * 16 + g;
            int col  = bn + n0 + nc * 8 + tq * 2;
            float b0 = bias[col], b1 = bias[col + 1];
            float v0 = acc[mi][nc][0] + b0, v1 = acc[mi][nc][1] + b1;
            float v2 = acc[mi][nc][2] + b0, v3 = acc[mi][nc][3] + b1;
            if (act) { v0 = gelu_f(v0); v1 = gelu_f(v1); v2 = gelu_f(v2); v3 = gelu_f(v3); }
            if (Cf) {
                *(float2*)(Cf + (size_t)row0 * N + col)       = make_float2(v0, v1);
                *(float2*)(Cf + (size_t)(row0 + 8) * N + col) = make_float2(v2, v3);
            } else {
                __nv_bfloat16 h0, l0, h1, l1;
                split2(v0, h0, l0); split2(v1, h1, l1);
                *(__nv_bfloat162*)(Chh + (size_t)row0 * N + col) = __nv_bfloat162(h0, h1);
                *(__nv_bfloat162*)(Cll + (size_t)row0 * N + col) = __nv_bfloat162(l0, l1);
                split2(v2, h0, l0); split2(v3, h1, l1);
                *(__nv_bfloat162*)(Chh + (size_t)(row0 + 8) * N + col) = __nv_bfloat162(h0, h1);
                *(__nv_bfloat162*)(Cll + (size_t)(row0 + 8) * N + col) = __nv_bfloat162(l0, l1);
            }
        }
    }
}

// ---------------- fused flash attention --------------------------------------
// grid (S/128 qtiles, B*H).  256 threads = 8 warps, warp w owns 16 q-rows.
// K-tiles of 128 keys, double-buffered.  Q,K,V read as bf16 hi/lo from g_qkv*.
// 3-pass mma for QK^T and PV; bias/mask/online-softmax on fragments.
#define FSMEM 163840
#define LOG2E 1.4426950408889634f

__global__ void __launch_bounds__(256, 1) k_flash(
    const int* __restrict__ seq, const int* __restrict__ squares,
    const float* __restrict__ dist_emb)
{
    extern __shared__ char smem[];
    const uint32_t sb = smem_u32(smem);
    const uint32_t oQh = 0, oQl = 16384, oK = 32768, oV = 98304;
    const int tid = threadIdx.x, wid = tid >> 5, lane = tid & 31;
    const int qt = blockIdx.x, bh = blockIdx.y, b = bh >> 3, h = bh & 7;

    // ---- load Q tile (once) + KV tile 0 ----
#pragma unroll
    for (int p = 0; p < 4; p++) {
        int t = tid + (p << 8);
        int r = t >> 3, c = t & 7;
        uint32_t sw = ((uint32_t)(c ^ (r & 7))) << 4;
        size_t goff = (size_t)(b * SS + qt * 128 + r) * E3 + h * DH + c * 8;
        cp16(sb + oQh + r * 128 + sw, g_qkvh + goff);
        cp16(sb + oQl + r * 128 + sw, g_qkvl + goff);
    }
    auto loadKV = [&](int kt) {
        uint32_t kb = sb + oK + (kt & 1) * 32768;
        uint32_t vb = sb + oV + (kt & 1) * 32768;
#pragma unroll
        for (int p = 0; p < 4; p++) {
            int t = tid + (p << 8);
            int r = t >> 3, c = t & 7;
            uint32_t sw = ((uint32_t)(c ^ (r & 7))) << 4;
            size_t base = (size_t)(b * SS + kt * 128 + r) * E3 + h * DH + c * 8;
            cp16(kb + r * 128 + sw,         g_qkvh + base + EE);
            cp16(kb + 16384 + r * 128 + sw, g_qkvl + base + EE);
            cp16(vb + r * 128 + sw,         g_qkvh + base + 2 * EE);
            cp16(vb + 16384 + r * 128 + sw, g_qkvl + base + 2 * EE);
        }
        cp_commit();
    };
    loadKV(0);   // commits Q + KV0 together

    // per-lane ldsm address components
    const int sub = lane >> 3;
    const int bro = ((sub >> 1) << 3) + (lane & 7);  // K B-frag row
    const int bck = sub & 1;                         // K B-frag k-chunk
    const int qrow = lane & 15;                      // Q A-frag row (within 16)
    const int qsel = lane >> 4;                      // Q A-frag k-chunk

    // state
    float O[8][4];
#pragma unroll
    for (int i = 0; i < 8; i++)
#pragma unroll
        for (int q = 0; q < 4; q++) O[i][q] = 0.0f;
    float m0 = -1e30f, m1 = -1e30f, l0 = 0.0f, l1 = 0.0f;
    uint32_t qfh[4][4], qfl[4][4];

    const int qi0 = qt * 128 + wid * 16 + (lane >> 2);
    const int* sqrow0 = squares + (size_t)(b * SS + qi0) * SS;
    const int* sqrow1 = squares + (size_t)(b * SS + qi0 + 8) * SS;
    const int* seqb = seq + b * SS;

    for (int kt = 0; kt < 4; kt++) {
        if (kt < 3) { loadKV(kt + 1); cp_wait<1>(); }
        else        { cp_wait<0>(); }
        __syncthreads();

        if (kt == 0) {
            // load Q fragments once (persist in registers)
#pragma unroll
            for (int ks = 0; ks < 4; ks++) {
                int r = wid * 16 + qrow;
                int ck = ks * 2 + qsel;
                uint32_t ad = sb + oQh + r * 128 + (((uint32_t)(ck ^ (r & 7))) << 4);
                ldsm4(qfh[ks], ad);
                ldsm4(qfl[ks], ad + 16384);
            }
        }

        const uint32_t kb = sb + oK + (kt & 1) * 32768;
        const uint32_t vb = sb + oV + (kt & 1) * 32768;

        // ---- S = Q K^T (3-pass) ----
        float S[16][4];
#pragma unroll
        for (int j = 0; j < 16; j++)
#pragma unroll
            for (int q = 0; q < 4; q++) S[j][q] = 0.0f;
#pragma unroll
        for (int ks = 0; ks < 4; ks++) {
#pragma unroll
            for (int ng = 0; ng < 8; ng++) {
                int r = ng * 16 + bro;
                int ck = ks * 2 + bck;
                uint32_t kd = kb + r * 128 + (((uint32_t)(ck ^ (r & 7))) << 4);
                uint32_t kh[4], kl[4];
                ldsm4(kh, kd);
                ldsm4(kl, kd + 16384);
                mma16816(S[2 * ng],     qfh[ks], kh);
                mma16816(S[2 * ng + 1], qfh[ks], kh + 2);
                mma16816(S[2 * ng],     qfh[ks], kl);
                mma16816(S[2 * ng + 1], qfh[ks], kl + 2);
                mma16816(S[2 * ng],     qfl[ks], kh);
                mma16816(S[2 * ng + 1], qfl[ks], kh + 2);
            }
        }

        // ---- bias + mask + tile row-max ----
        const int kbase = kt * 128;
        float tm0 = -1e30f, tm1 = -1e30f;
#pragma unroll
        for (int j = 0; j < 16; j++) {
            int kj = kbase + j * 8 + ((lane & 3) << 1);
            float msk0 = (seqb[kj] == 0)     ? -1e9f : 0.0f;
            float msk1 = (seqb[kj + 1] == 0) ? -1e9f : 0.0f;
            float b00 = dist_emb[sqrow0[kj] * HH + h]     + msk0;
            float b01 = dist_emb[sqrow0[kj + 1] * HH + h] + msk1;
            float b10 = dist_emb[sqrow1[kj] * HH + h]     + msk0;
            float b11 = dist_emb[sqrow1[kj + 1] * HH + h] + msk1;
            S[j][0] = fmaf(S[j][0], 0.125f, b00);
            S[j][1] = fmaf(S[j][1], 0.125f, b01);
            S[j][2] = fmaf(S[j][2], 0.125f, b10);
            S[j][3] = fmaf(S[j][3], 0.125f, b11);
            tm0 = fmaxf(tm0, fmaxf(S[j][0], S[j][1]));
            tm1 = fmaxf(tm1, fmaxf(S[j][2], S[j][3]));
        }
        tm0 = fmaxf(tm0, __shfl_xor_sync(0xffffffffu, tm0, 1));
        tm0 = fmaxf(tm0, __shfl_xor_sync(0xffffffffu, tm0, 2));
        tm1 = fmaxf(tm1, __shfl_xor_sync(0xffffffffu, tm1, 1));
        tm1 = fmaxf(tm1, __shfl_xor_sync(0xffffffffu, tm1, 2));

        // ---- online softmax update ----
        float mn0 = fmaxf(m0, tm0), mn1 = fmaxf(m1, tm1);
        float al0 = exp2f((m0 - mn0) * LOG2E), al1 = exp2f((m1 - mn1) * LOG2E);
        m0 = mn0; m1 = mn1;
        float ts0 = 0.0f, ts1 = 0.0f;
#pragma unroll
        for (int j = 0; j < 16; j++) {
            S[j][0] = exp2f((S[j][0] - mn0) * LOG2E);
            S[j][1] = exp2f((S[j][1] - mn0) * LOG2E);
            S[j][2] = exp2f((S[j][2] - mn1) * LOG2E);
            S[j][3] = exp2f((S[j][3] - mn1) * LOG2E);
            ts0 += S[j][0] + S[j][1];
            ts1 += S[j][2] + S[j][3];
        }
        ts0 += __shfl_xor_sync(0xffffffffu, ts0, 1);
        ts0 += __shfl_xor_sync(0xffffffffu, ts0, 2);
        ts1 += __shfl_xor_sync(0xffffffffu, ts1, 1);
        ts1 += __shfl_xor_sync(0xffffffffu, ts1, 2);
        l0 = l0 * al0 + ts0;
        l1 = l1 * al1 + ts1;
#pragma unroll
        for (int i = 0; i < 8; i++) {
            O[i][0] *= al0; O[i][1] *= al0;
            O[i][2] *= al1; O[i][3] *= al1;
        }

        // ---- O += P V (3-pass, P split hi/lo in regs) ----
#pragma unroll
        for (int kk = 0; kk < 8; kk++) {
            uint32_t pah[4], pal[4];
            {
                float c0 = S[2 * kk][0], c1 = S[2 * kk][1];
                float c2 = S[2 * kk][2], c3 = S[2 * kk][3];
                float d0 = S[2 * kk + 1][0], d1 = S[2 * kk + 1][1];
                float d2 = S[2 * kk + 1][2], d3 = S[2 * kk + 1][3];
                __nv_bfloat16 hh_, ll_;
                float h0, h1, h2, h3, e0, e1, e2, e3;
                split2(c0, hh_, ll_); h0 = __bfloat162float(hh_); e0 = __bfloat162float(ll_);
                split2(c1, hh_, ll_); h1 = __bfloat162float(hh_); e1 = __bfloat162float(ll_);
                split2(c2, hh_, ll_); h2 = __bfloat162float(hh_); e2 = __bfloat162float(ll_);
                split2(c3, hh_, ll_); h3 = __bfloat162float(hh_); e3 = __bfloat162float(ll_);
                pah[0] = packbf2(h0, h1); pah[1] = packbf2(h2, h3);
                pal[0] = packbf2(e0, e1); pal[1] = packbf2(e2, e3);
                split2(d0, hh_, ll_); h0 = __bfloat162float(hh_); e0 = __bfloat162float(ll_);
                split2(d1, hh_, ll_); h1 = __bfloat162float(hh_); e1 = __bfloat162float(ll_);
                split2(d2, hh_, ll_); h2 = __bfloat162float(hh_); e2 = __bfloat162float(ll_);
                split2(d3, hh_, ll_); h3 = __bfloat162float(hh_); e3 = __bfloat162float(ll_);
                pah[2] = packbf2(h0, h1); pah[3] = packbf2(h2, h3);
                pal[2] = packbf2(e0, e1); pal[3] = packbf2(e2, e3);
            }
            int vrow = kk * 16 + (lane & 15);
#pragma unroll
            for (int vg = 0; vg < 4; vg++) {
                int vchunk = vg * 2 + (lane >> 4);
                uint32_t vd = vb + vrow * 128 + (((uint32_t)(vchunk ^ (vrow & 7))) << 4);
                uint32_t vh[4], vl[4];
                ldsm4t(vh, vd);
                ldsm4t(vl, vd + 16384);
                mma16816(O[2 * vg],     pah, vh);
                mma16816(O[2 * vg + 1], pah, vh + 2);
                mma16816(O[2 * vg],     pah, vl);
                mma16816(O[2 * vg + 1], pah, vl + 2);
                mma16816(O[2 * vg],     pal, vh);
                mma16816(O[2 * vg + 1], pal, vh + 2);
            }
        }
        __syncthreads();
    }

    // ---- finalize: divide by row sum, write ctx hi/lo ----
    float inv0 = 1.0f / l0, inv1 = 1.0f / l1;
#pragma unroll
    for (int jo = 0; jo < 8; jo++) {
        int dh0 = jo * 8 + ((lane & 3) << 1);
        float v0 = O[jo][0] * inv0, v1 = O[jo][1] * inv0;
        float v2 = O[jo][2] * inv1, v3 = O[jo][3] * inv1;
        size_t o0 = (size_t)(b * SS + qi0) * EE + h * DH + dh0;
        size_t o1 = (size_t)(b * SS + qi0 + 8) * EE + h * DH + dh0;
        __nv_bfloat16 h0, e0, h1, e1;
        split2(v0, h0, e0); split2(v1, h1, e1);
        *(__nv_bfloat162*)(g_cxh + o0) = __nv_bfloat162(h0, h1);
        *(__nv_bfloat162*)(g_cxl + o0) = __nv_bfloat162(e0, e1);
        split2(v2, h0, e0); split2(v3, h1, e1);
        *(__nv_bfloat162*)(g_cxh + o1) = __nv_bfloat162(h0, h1);
        *(__nv_bfloat162*)(g_cxl + o1) = __nv_bfloat162(e0, e1);
    }
}

// ---------------- residual + LayerNorm, fp32 + bf16 hi/lo --------------------
__global__ void __launch_bounds__(256) k_ln_res(
    const float* __restrict__ res, const float* __restrict__ add,
    const float* __restrict__ w, const float* __restrict__ bb,
    float* __restrict__ out)
{
    const int row = blockIdx.x, tid = threadIdx.x;
    const int lane = tid & 31, wid = tid >> 5;
    __shared__ float r1[8], r2[8];

    size_t base = (size_t)row * EE;
    float v0 = res[base + tid] + add[base + tid];
    float v1 = res[base + tid + 256] + add[base + tid + 256];
    float s = v0 + v1, s2 = v0 * v0 + v1 * v1;
#pragma unroll
    for (int o = 16; o > 0; o >>= 1) {
        s  += __shfl_xor_sync(0xffffffffu, s, o);
        s2 += __shfl_xor_sync(0xffffffffu, s2, o);
    }
    if (lane == 0) { r1[wid] = s; r2[wid] = s2; }
    __syncthreads();
    s = r1[0]; s2 = r2[0];
#pragma unroll
    for (int i = 1; i < 8; i++) { s += r1[i]; s2 += r2[i]; }
    float mean = s * (1.0f / EE);
    float var  = s2 * (1.0f / EE) - mean * mean;
    float inv = rsqrtf(var + 1e-5f);
    float o0 = (v0 - mean) * inv * w[tid] + bb[tid];
    float o1 = (v1 - mean) * inv * w[tid + 256] + bb[tid + 256];
    out[base + tid] = o0;
    out[base + tid + 256] = o1;
    __nv_bfloat16 h16, l16;
    split2(o0, h16, l16); g_xh[base + tid] = h16;       g_xl[base + tid] = l16;
    split2(o1, h16, l16); g_xh[base + tid + 256] = h16; g_xl[base + tid + 256] = l16;
}

// ---------------- final LN -> out[(s,b,e)] -----------------------------------
__global__ void __launch_bounds__(256) k_ln_final(
    const float* __restrict__ w, const float* __restrict__ bb,
    float* __restrict__ out)
{
    const int row = blockIdx.x, tid = threadIdx.x;
    const int b = row >> 9, sPos = row & 511;
    const int lane = tid & 31, wid = tid >> 5;
    __shared__ float r1[8], r2[8];

    size_t base = (size_t)row * EE;
    float v0 = g_x[base + tid];
    float v1 = g_x[base + tid + 256];
    float s = v0 + v1, s2 = v0 * v0 + v1 * v1;
#pragma unroll
    for (int o = 16; o > 0; o >>= 1) {
        s  += __shfl_xor_sync(0xffffffffu, s, o);
        s2 += __shfl_xor_sync(0xffffffffu, s2, o);
    }
    if (lane == 0) { r1[wid] = s; r2[wid] = s2; }
    __syncthreads();
    s = r1[0]; s2 = r2[0];
#pragma unroll
    for (int i = 1; i < 8; i++) { s += r1[i]; s2 += r2[i]; }
    float mean = s * (1.0f / EE);
    float var  = s2 * (1.0f / EE) - mean * mean;
    float inv = rsqrtf(var + 1e-5f);
    size_t o = ((size_t)sPos * Bq + b) * EE;
    out[o + tid]       = (v0 - mean) * inv * w[tid] + bb[tid];
    out[o + tid + 256] = (v1 - mean) * inv * w[tid + 256] + bb[tid + 256];
}

// ---------------- key padding mask -------------------------------------------
__global__ void k_mask(const int* __restrict__ seq, float* __restrict__ out) {
    int idx = blockIdx.x * blockDim.x + threadIdx.x;
    if (idx < Bq * SS) out[idx] = (seq[idx] == 0) ? 1.0f : 0.0f;
}

// ---------------- launch -----------------------------------------------------
extern "C" void kernel_launch(void* const* d_in, const int* in_sizes, int n_in,
                              void* d_out, int out_size)
{
    const int*   seq       = (const int*)d_in[0];
    const int*   squares   = (const int*)d_in[1];
    const float* tok_emb   = (const float*)d_in[2];
    const float* dist_emb  = (const float*)d_in[3];
    const float* in_proj_w = (const float*)d_in[4];
    const float* in_proj_b = (const float*)d_in[5];
    const float* out_w     = (const float*)d_in[6];
    const float* out_b     = (const float*)d_in[7];
    const float* ff1_w     = (const float*)d_in[8];
    const float* ff1_b     = (const float*)d_in[9];
    const float* ff2_w     = (const float*)d_in[10];
    const float* ff2_b     = (const float*)d_in[11];
    const float* ln1_w     = (const float*)d_in[12];
    const float* ln1_b     = (const float*)d_in[13];
    const float* ln2_w     = (const float*)d_in[14];
    const float* ln2_b     = (const float*)d_in[15];
    const float* lnf_w     = (const float*)d_in[16];
    const float* lnf_b     = (const float*)d_in[17];
    float* out = (float*)d_out;

    float *x, *att, *ffb;
    cudaGetSymbolAddress((void**)&x,   g_x);
    cudaGetSymbolAddress((void**)&att, g_att);
    cudaGetSymbolAddress((void**)&ffb, g_ff);
    __nv_bfloat16 *xh, *xl, *cxh, *cxl, *hh, *hl, *qvh, *qvl;
    __nv_bfloat16 *wqh, *wql, *woh, *wol, *f1h, *f1l, *f2h, *f2l;
    cudaGetSymbolAddress((void**)&xh,  g_xh);  cudaGetSymbolAddress((void**)&xl,  g_xl);
    cudaGetSymbolAddress((void**)&cxh, g_cxh); cudaGetSymbolAddress((void**)&cxl, g_cxl);
    cudaGetSymbolAddress((void**)&hh,  g_hh);  cudaGetSymbolAddress((void**)&hl,  g_hl);
    cudaGetSymbolAddress((void**)&qvh, g_qkvh); cudaGetSymbolAddress((void**)&qvl, g_qkvl);
    cudaGetSymbolAddress((void**)&wqh, g_wqh); cudaGetSymbolAddress((void**)&wql, g_wql);
    cudaGetSymbolAddress((void**)&woh, g_woh); cudaGetSymbolAddress((void**)&wol, g_wol);
    cudaGetSymbolAddress((void**)&f1h, g_f1h); cudaGetSymbolAddress((void**)&f1l, g_f1l);
    cudaGetSymbolAddress((void**)&f2h, g_f2h); cudaGetSymbolAddress((void**)&f2l, g_f2l);

    cudaFuncSetAttribute(k_mmagemm, cudaFuncAttributeMaxDynamicSharedMemorySize, GSMEM);
    cudaFuncSetAttribute(k_flash,   cudaFuncAttributeMaxDynamicSharedMemorySize, FSMEM);

    // split weights
    { int n = LL * E3 * EE; k_split<<<(n + 255) / 256, 256>>>(in_proj_w, wqh, wql, n); }
    { int n = LL * EE * EE; k_split<<<(n + 255) / 256, 256>>>(out_w, woh, wol, n); }
    { int n = LL * FF * EE; k_split<<<(n + 255) / 256, 256>>>(ff1_w, f1h, f1l, n); }
    { int n = LL * EE * FF; k_split<<<(n + 255) / 256, 256>>>(ff2_w, f2h, f2l, n); }

    // embedding
    k_embed<<<(NTOK * EE + 255) / 256, 256>>>(seq, tok_emb);

    for (int l = 0; l < LL; l++) {
        // qkv projection -> bf16 hi/lo directly
        k_mmagemm<<<dim3(E3 / 128, NTOK / 128), 256, GSMEM>>>(
            xh, xl, wqh + (size_t)l * E3 * EE, wql + (size_t)l * E3 * EE,
            in_proj_b + (size_t)l * E3, nullptr, qvh, qvl, E3, EE, 0);
        // fused attention (scores + bias + mask + softmax + PV)
        k_flash<<<dim3(SS / 128, Bq * HH), 256, FSMEM>>>(seq, squares, dist_emb);
        // out projection
        k_mmagemm<<<dim3(EE / 128, NTOK / 128), 256, GSMEM>>>(
            cxh, cxl, woh + (size_t)l * EE * EE, wol + (size_t)l * EE * EE,
            out_b + (size_t)l * EE, att, nullptr, nullptr, EE, EE, 0);
        // ln1
        k_ln_res<<<NTOK, 256>>>(x, att, ln1_w + (size_t)l * EE, ln1_b + (size_t)l * EE, x);
        // ff1 + gelu (bf16 hi/lo out)
        k_mmagemm<<<dim3(FF / 128, NTOK / 128), 256, GSMEM>>>(
            xh, xl, f1h + (size_t)l * FF * EE, f1l + (size_t)l * FF * EE,
            ff1_b + (size_t)l * FF, nullptr, hh, hl, FF, EE, 1);
        // ff2
        k_mmagemm<<<dim3(EE / 128, NTOK / 128), 256, GSMEM>>>(
            hh, hl, f2h + (size_t)l * EE * FF, f2l + (size_t)l * EE * FF,
            ff2_b + (size_t)l * EE, ffb, nullptr, nullptr, EE, FF, 0);
        // ln2
        k_ln_res<<<NTOK, 256>>>(x, ffb, ln2_w + (size_t)l * EE, ln2_b + (size_t)l * EE, x);
    }

    // final LN + transpose to [S,B,E]
    k_ln_final<<<NTOK, 256>>>(lnf_w, lnf_b, out);

    if (out_size >= NTOK * EE + Bq * SS) {
        k_mask<<<(Bq * SS + 255) / 256, 256>>>(seq, out + (size_t)NTOK * EE);
    }
}